// round 13
// baseline (speedup 1.0000x reference)
#include <cuda_runtime.h>

#define BATCH   16
#define EPSV    1e-5f
#define SLICES  74               // 16*74 = 1184 = 148 SMs * 8 blocks: ONE exact wave
#define TPB     256
#define STRIDE  (SLICES * TPB)   // quad stride per segment sweep

// Global scratch (allocation-free: __device__ arrays)
__device__ float g_sum[BATCH * 16];
__device__ float g_ssq[BATCH * 16];
__device__ int   g_start[BATCH + 1]; // segment starts in sorted batch_id

// Setup: zero accumulators + per-warp 32-ary search for the 15 boundaries.
// A serial binary search is 20 DEPENDENT probes (~13us measured in R6); the
// full pairwise scan fixed the dependence but paid a 4MB read + 262K-thread
// launch (5.7us, latency-bound). 32-ary search: 4-5 dependent rounds of 32
// PARALLEL probes each -> ~1.7us for all 15 boundaries in one small block.
__global__ void ogn_setup_kernel(const int* __restrict__ batch_id, int nrows) {
    const int t    = threadIdx.x;     // 512 threads = 16 warps
    const int w    = t >> 5;
    const int lane = t & 31;

    if (t < BATCH * 16) { g_sum[t] = 0.f; g_ssq[t] = 0.f; }
    if (t == 0) { g_start[0] = 0; g_start[BATCH] = nrows; }

    const int v = w;                  // warp w finds g_start[v], v = 1..15
    if (v >= 1 && v < BATCH) {
        if (__ldg(&batch_id[0]) >= v) {
            if (lane == 0) g_start[v] = 0;          // leading empty batches
        } else {
            // invariant: batch_id[lo] < v, answer (first idx >= v) in (lo, hi]
            int lo = 0, hi = nrows;
            while (hi - lo > 32) {
                const int len = hi - lo;            // <= nrows, len*31 fits int
                const int pk  = lo + ((len * lane) >> 5);
                const int pk1 = lo + ((len * (lane + 1)) >> 5);
                const int a   = __ldg(&batch_id[pk]);
                unsigned bal = __ballot_sync(0xffffffffu, a < v);
                // lane 0 probes lo where batch_id[lo] < v, so bal != 0
                const int j = 31 - __clz(bal);      // highest lane with a < v
                lo = __shfl_sync(0xffffffffu, pk,  j);
                hi = __shfl_sync(0xffffffffu, pk1, j);
            }
            // final: candidates lo+1 .. hi (len <= 32); probe interior points
            const int len = hi - lo;
            bool ge = false;
            if (lane < len - 1) ge = (__ldg(&batch_id[lo + 1 + lane]) >= v);
            unsigned bal = __ballot_sync(0xffffffffu, ge);
            const int res = bal ? (lo + 1 + (__ffs(bal) - 1)) : hi;
            if (lane == 0) g_start[v] = res;
        }
    }
}

// Pass 1: per-(batch, group) sum / sum-of-squares.
// Single-wave geometry (1184 blocks @ 8/SM), segment-aligned strided FORWARD
// sweep (leaves each segment's tail hot in L2 for pass2's reverse sweep).
__global__ void __launch_bounds__(TPB, 8)
ogn_pass1_kernel(const float4* __restrict__ data4) {
    const int t     = threadIdx.x;
    const int g     = t & 15;
    const int b     = blockIdx.x & (BATCH - 1);
    const int slice = blockIdx.x >> 4;

    const int q1 = g_start[b + 1] * 16;
    int qi = g_start[b] * 16 + slice * TPB + t;

    float s0 = 0.f, s1 = 0.f, qa = 0.f, qb = 0.f;
    #pragma unroll 2
    for (; qi + STRIDE < q1; qi += 2 * STRIDE) {
        float4 va = data4[qi];
        float4 vb = data4[qi + STRIDE];
        s0 += (va.x + va.y) + (va.z + va.w);
        qa += va.x * va.x + va.y * va.y + va.z * va.z + va.w * va.w;
        s1 += (vb.x + vb.y) + (vb.z + vb.w);
        qb += vb.x * vb.x + vb.y * vb.y + vb.z * vb.z + vb.w * vb.w;
    }
    if (qi < q1) {                      // at most one straggler
        float4 v = data4[qi];
        s0 += (v.x + v.y) + (v.z + v.w);
        qa += v.x * v.x + v.y * v.y + v.z * v.z + v.w * v.w;
    }
    float gsum = s0 + s1;
    float gssq = qa + qb;

    // lanes t and t+16 in each warp share g: fold, then cross-warp via shared.
    gsum += __shfl_xor_sync(0xffffffffu, gsum, 16);
    gssq += __shfl_xor_sync(0xffffffffu, gssq, 16);

    __shared__ float sh_sum[8][16];
    __shared__ float sh_ssq[8][16];
    const int w = t >> 5;
    if ((t & 31) < 16) { sh_sum[w][g] = gsum; sh_ssq[w][g] = gssq; }
    __syncthreads();

    if (t < 16) {
        float s = 0.f, q = 0.f;
        #pragma unroll
        for (int i = 0; i < 8; i++) { s += sh_sum[i][t]; q += sh_ssq[i][t]; }
        if (s != 0.f || q != 0.f) {
            atomicAdd(&g_sum[b * 16 + t], s);
            atomicAdd(&g_ssq[b * 16 + t], q);
        }
    }
}

// Pass 2: out = x * A[b][c] + B[b][c].
// Single-wave geometry. Inline per-block stats -> register A/B, then a
// REVERSE sweep of this segment so the lines pass1 just left in L2 are
// consumed first. __ldcs/__stcs keep both streams evict-first.
__global__ void __launch_bounds__(TPB, 8)
ogn_pass2_kernel(const float4* __restrict__ data4,
                 float4* __restrict__ out4,
                 const float* __restrict__ weights,
                 const float* __restrict__ bias) {
    __shared__ float smean[16], sistd[16];
    const int t     = threadIdx.x;
    const int g     = t & 15;
    const int b     = blockIdx.x & (BATCH - 1);
    const int slice = blockIdx.x >> 4;

    const int r0 = g_start[b];
    const int r1 = g_start[b + 1];

    if (t < 16) {
        float n = (float)(r1 - r0);
        float inv_count = 1.f / (n * 4.f + EPSV);
        float s = g_sum[b * 16 + t], q = g_ssq[b * 16 + t];
        float m = s * inv_count;
        float var = (q - 2.f * m * s + 4.f * n * m * m) * inv_count;
        smean[t] = m;
        sistd[t] = rsqrtf(var + EPSV);
    }
    __syncthreads();

    const float4 w4  = __ldg(&((const float4*)weights)[g]);
    const float4 bi4 = __ldg(&((const float4*)bias)[g]);
    const float istd = sistd[g];
    const float m    = smean[g];
    float4 a, bb;
    a.x = istd * w4.x;  a.y = istd * w4.y;  a.z = istd * w4.z;  a.w = istd * w4.w;
    bb.x = bi4.x - m * a.x;  bb.y = bi4.y - m * a.y;
    bb.z = bi4.z - m * a.z;  bb.w = bi4.w - m * a.w;

    const int base = r0 * 16 + slice * TPB + t;
    const int span = r1 * 16 - base;
    if (span > 0) {
        const int kmax = (span + STRIDE - 1) / STRIDE;   // const divisor -> mul/shift
        #pragma unroll 2
        for (int k = kmax - 1; k >= 0; --k) {   // reverse: consume hot L2 tail first
            const int qi = base + k * STRIDE;
            float4 v = __ldcs(&data4[qi]);
            float4 o;
            o.x = fmaf(v.x, a.x, bb.x);
            o.y = fmaf(v.y, a.y, bb.y);
            o.z = fmaf(v.z, a.z, bb.z);
            o.w = fmaf(v.w, a.w, bb.w);
            __stcs(&out4[qi], o);
        }
    }
}

extern "C" void kernel_launch(void* const* d_in, const int* in_sizes, int n_in,
                              void* d_out, int out_size) {
    const float* data     = (const float*)d_in[0];
    const int*   batch_id = (const int*)d_in[1];
    const float* weights  = (const float*)d_in[2];
    const float* bias     = (const float*)d_in[3];
    float*       out      = (float*)d_out;
    const int    nrows    = in_sizes[1];          // batch_id element count = N

    ogn_setup_kernel<<<1, 512>>>(batch_id, nrows);
    ogn_pass1_kernel<<<BATCH * SLICES, TPB>>>((const float4*)data);
    ogn_pass2_kernel<<<BATCH * SLICES, TPB>>>((const float4*)data, (float4*)out,
                                              weights, bias);
}

// round 14
// speedup vs baseline: 1.0096x; 1.0096x over previous
#include <cuda_runtime.h>

#define BATCH   16
#define EPSV    1e-5f
#define SLICES  74               // 16*74 = 1184 = 148 SMs * 8 blocks: ONE exact wave
#define TPB     256
#define GRID    (BATCH * SLICES)
#define STRIDE  (SLICES * TPB)   // quad stride per segment sweep

// Per-block partials, written UNCONDITIONALLY by every pass1 block every run:
// no atomics, no zero-init kernel, replay-safe by construction.
__device__ float g_psum[GRID * 16];
__device__ float g_pssq[GRID * 16];

// Warp-cooperative 32-ary search: first idx with batch_id[idx] >= v.
// ~5 dependent rounds of 32 parallel probes (verified correct in R13).
// Warp-uniform v; full-warp participation required.
__device__ __forceinline__ int find_start(const int* __restrict__ batch_id,
                                          int nrows, int v) {
    const int lane = threadIdx.x & 31;
    if (v <= 0) return 0;
    if (v >= BATCH) return nrows;
    if (__ldg(&batch_id[0]) >= v) return 0;          // leading empty batches
    // invariant: batch_id[lo] < v, answer in (lo, hi]
    int lo = 0, hi = nrows;
    while (hi - lo > 32) {
        const int len = hi - lo;
        const int pa = lo + (int)(((long long)len * lane) >> 5);
        const int pb = lo + (int)(((long long)len * (lane + 1)) >> 5);
        const int a  = __ldg(&batch_id[pa]);
        unsigned bal = __ballot_sync(0xffffffffu, a < v);
        const int j = 31 - __clz(bal);               // highest lane with a < v
        lo = __shfl_sync(0xffffffffu, pa, j);
        hi = __shfl_sync(0xffffffffu, pb, j);
    }
    const int len = hi - lo;
    bool ge = (lane < len - 1) ? (__ldg(&batch_id[lo + 1 + lane]) >= v) : false;
    unsigned bal = __ballot_sync(0xffffffffu, ge);
    return bal ? (lo + __ffs(bal)) : hi;
}

// Pass 1: inline boundary search, then per-(batch, group) sum / ssq.
// Single-wave geometry, segment-aligned strided FORWARD sweep (leaves each
// segment's tail hot in L2 for pass2's reverse sweep).
__global__ void __launch_bounds__(TPB, 8)
ogn_pass1_kernel(const float4* __restrict__ data4,
                 const int*    __restrict__ batch_id,
                 int nrows) {
    __shared__ int sb[2];
    const int t     = threadIdx.x;
    const int g     = t & 15;
    const int w     = t >> 5;
    const int b     = blockIdx.x & (BATCH - 1);
    const int slice = blockIdx.x >> 4;

    if (w < 2) {
        int r = find_start(batch_id, nrows, b + w);
        if ((t & 31) == 0) sb[w] = r;
    }
    __syncthreads();
    const int r0 = sb[0], r1 = sb[1];

    const int q1 = r1 * 16;
    int qi = r0 * 16 + slice * TPB + t;

    float s0 = 0.f, s1 = 0.f, qa = 0.f, qb = 0.f;
    #pragma unroll 2
    for (; qi + STRIDE < q1; qi += 2 * STRIDE) {
        float4 va = data4[qi];
        float4 vb = data4[qi + STRIDE];
        s0 += (va.x + va.y) + (va.z + va.w);
        qa += va.x * va.x + va.y * va.y + va.z * va.z + va.w * va.w;
        s1 += (vb.x + vb.y) + (vb.z + vb.w);
        qb += vb.x * vb.x + vb.y * vb.y + vb.z * vb.z + vb.w * vb.w;
    }
    if (qi < q1) {                      // at most one straggler
        float4 v = data4[qi];
        s0 += (v.x + v.y) + (v.z + v.w);
        qa += v.x * v.x + v.y * v.y + v.z * v.z + v.w * v.w;
    }
    float gsum = s0 + s1;
    float gssq = qa + qb;

    // lanes t and t+16 in each warp share g: fold, then cross-warp via shared.
    gsum += __shfl_xor_sync(0xffffffffu, gsum, 16);
    gssq += __shfl_xor_sync(0xffffffffu, gssq, 16);

    __shared__ float sh_sum[8][16];
    __shared__ float sh_ssq[8][16];
    if ((t & 31) < 16) { sh_sum[w][g] = gsum; sh_ssq[w][g] = gssq; }
    __syncthreads();

    if (t < 16) {
        float s = 0.f, q = 0.f;
        #pragma unroll
        for (int i = 0; i < 8; i++) { s += sh_sum[i][t]; q += sh_ssq[i][t]; }
        g_psum[blockIdx.x * 16 + t] = s;   // unconditional: replay-safe
        g_pssq[blockIdx.x * 16 + t] = q;
    }
}

// Pass 2: warps 0-1 re-run the (now L2-hot) boundary search while warps 2-7
// reduce this batch's 74x16 partials; then stats -> register affine, and a
// REVERSE sweep so the lines pass1 just left in L2 are consumed first.
__global__ void __launch_bounds__(TPB, 8)
ogn_pass2_kernel(const float4* __restrict__ data4,
                 float4*       __restrict__ out4,
                 const int*    __restrict__ batch_id,
                 const float*  __restrict__ weights,
                 const float*  __restrict__ bias,
                 int nrows) {
    __shared__ int   sb[2];
    __shared__ float sh_s[12][16], sh_q[12][16];
    __shared__ float smean[16], sistd[16];
    const int t     = threadIdx.x;
    const int g     = t & 15;
    const int w     = t >> 5;
    const int b     = blockIdx.x & (BATCH - 1);
    const int slice = blockIdx.x >> 4;

    if (w < 2) {
        int r = find_start(batch_id, nrows, b + w);
        if ((t & 31) == 0) sb[w] = r;
    } else {
        // warps 2-7 (192 threads = 12 x 16): reduce partials for batch b
        const int idx = t - 64;
        const int rl  = idx >> 4;           // 0..11
        const int gg  = idx & 15;
        float s = 0.f, q = 0.f;
        for (int sl = rl; sl < SLICES; sl += 12) {
            const int p = (b + 16 * sl) * 16 + gg;
            s += __ldg(&g_psum[p]);
            q += __ldg(&g_pssq[p]);
        }
        sh_s[rl][gg] = s;
        sh_q[rl][gg] = q;
    }
    __syncthreads();
    const int r0 = sb[0], r1 = sb[1];

    if (t < 16) {
        float s = 0.f, q = 0.f;
        #pragma unroll
        for (int i = 0; i < 12; i++) { s += sh_s[i][t]; q += sh_q[i][t]; }
        float n = (float)(r1 - r0);
        float inv_count = 1.f / (n * 4.f + EPSV);
        float m = s * inv_count;
        float var = (q - 2.f * m * s + 4.f * n * m * m) * inv_count;
        smean[t] = m;
        sistd[t] = rsqrtf(var + EPSV);
    }
    __syncthreads();

    const float4 w4  = __ldg(&((const float4*)weights)[g]);
    const float4 bi4 = __ldg(&((const float4*)bias)[g]);
    const float istd = sistd[g];
    const float m    = smean[g];
    float4 a, bb;
    a.x = istd * w4.x;  a.y = istd * w4.y;  a.z = istd * w4.z;  a.w = istd * w4.w;
    bb.x = bi4.x - m * a.x;  bb.y = bi4.y - m * a.y;
    bb.z = bi4.z - m * a.z;  bb.w = bi4.w - m * a.w;

    const int base = r0 * 16 + slice * TPB + t;
    const int span = r1 * 16 - base;
    if (span > 0) {
        const int kmax = (span + STRIDE - 1) / STRIDE;   // const divisor -> mul/shift
        #pragma unroll 2
        for (int k = kmax - 1; k >= 0; --k) {   // reverse: consume hot L2 tail first
            const int qi = base + k * STRIDE;
            float4 v = __ldcs(&data4[qi]);
            float4 o;
            o.x = fmaf(v.x, a.x, bb.x);
            o.y = fmaf(v.y, a.y, bb.y);
            o.z = fmaf(v.z, a.z, bb.z);
            o.w = fmaf(v.w, a.w, bb.w);
            __stcs(&out4[qi], o);
        }
    }
}

extern "C" void kernel_launch(void* const* d_in, const int* in_sizes, int n_in,
                              void* d_out, int out_size) {
    const float* data     = (const float*)d_in[0];
    const int*   batch_id = (const int*)d_in[1];
    const float* weights  = (const float*)d_in[2];
    const float* bias     = (const float*)d_in[3];
    float*       out      = (float*)d_out;
    const int    nrows    = in_sizes[1];          // batch_id element count = N

    ogn_pass1_kernel<<<GRID, TPB>>>((const float4*)data, batch_id, nrows);
    ogn_pass2_kernel<<<GRID, TPB>>>((const float4*)data, (float4*)out,
                                    batch_id, weights, bias, nrows);
}